// round 6
// baseline (speedup 1.0000x reference)
#include <cuda_runtime.h>

// Row-wise normalization: out[r, :] = in[r, :] / sum(in[r, :])
// Rows = 2*32*1024 = 65536, row length = 1024 floats = 256 float4.
//
// PERSISTENT version: one warp per row via grid-stride over rows.
// Grid = 148 SMs * 5 resident blocks (regs=48 => 5 blocks/SM cap), so the
// whole kernel is a single wave: no wave-transition bubbles, minimal tail.
// Body: 32 lanes x 8 coalesced float4 in registers, warp-shuffle reduce,
// streaming (.cs) load/store — each element touches HBM exactly twice.
__global__ void __launch_bounds__(256)
normalizer_kernel(const float4* __restrict__ in, float4* __restrict__ out,
                  unsigned nrows) {
    const unsigned warps_per_blk = blockDim.x >> 5;                 // 8
    const unsigned lane   = threadIdx.x & 31u;
    unsigned       row    = blockIdx.x * warps_per_blk + (threadIdx.x >> 5);
    const unsigned stride = gridDim.x * warps_per_blk;

    for (; row < nrows; row += stride) {
        const float4* __restrict__ rp = in  + (size_t)row * 256u + lane;
        float4*       __restrict__ wp = out + (size_t)row * 256u + lane;

        float4 v[8];
        #pragma unroll
        for (int k = 0; k < 8; k++)
            v[k] = __ldcs(rp + 32 * k);          // 8 independent LDG.128

        float s = 0.0f;
        #pragma unroll
        for (int k = 0; k < 8; k++)
            s += (v[k].x + v[k].y) + (v[k].z + v[k].w);

        #pragma unroll
        for (int off = 16; off > 0; off >>= 1)
            s += __shfl_xor_sync(0xffffffffu, s, off);

        float inv = 1.0f / s;
        if (!isfinite(inv)) inv = 0.0f;          // reference: remove_nan_inf

        #pragma unroll
        for (int k = 0; k < 8; k++) {
            v[k].x *= inv; v[k].y *= inv; v[k].z *= inv; v[k].w *= inv;
            __stcs(wp + 32 * k, v[k]);
        }
    }
}

extern "C" void kernel_launch(void* const* d_in, const int* in_sizes, int n_in,
                              void* d_out, int out_size) {
    (void)in_sizes; (void)n_in; (void)out_size;
    const float4* in  = (const float4*)d_in[0];
    float4*       out = (float4*)d_out;

    const unsigned n_rows = 2u * 32u * 1024u;    // 65536
    // One full resident wave: 148 SMs x 5 blocks (48-reg occupancy cap).
    const unsigned grid = 148u * 5u;
    normalizer_kernel<<<grid, 256>>>(in, out, n_rows);
}

// round 8
// speedup vs baseline: 1.0014x; 1.0014x over previous
#include <cuda_runtime.h>

// Row-wise normalization: out[r, :] = in[r, :] / sum(in[r, :])
// Rows = 2*32*1024 = 65536, row length = 1024 floats = 256 float4.
//
// Persistent, SOFTWARE-PIPELINED: one warp per row, double-buffered so the
// next row's 8 LDG.128 are in flight while the current row is reduced,
// scaled and stored. This hides the shuffle-reduce + store chain under
// DRAM latency continuously (R6 showed the non-pipelined persistent loop
// serializes across iterations and loses MLP).
__global__ void __launch_bounds__(256, 3)
normalizer_kernel(const float4* __restrict__ in, float4* __restrict__ out,
                  unsigned nrows) {
    const unsigned lane   = threadIdx.x & 31u;
    const unsigned stride = (gridDim.x * blockDim.x) >> 5;   // total warps
    unsigned row = (blockIdx.x * blockDim.x + threadIdx.x) >> 5;

    if (row >= nrows) return;

    float4 cur[8];
    {
        const float4* __restrict__ rp = in + (size_t)row * 256u + lane;
        #pragma unroll
        for (int k = 0; k < 8; k++) cur[k] = __ldcs(rp + 32 * k);
    }

    for (;;) {
        const unsigned next = row + stride;
        const bool has_next = next < nrows;

        // Prefetch next row FIRST — these 8 independent LDG.128 overlap the
        // reduction + stores below.
        float4 nxt[8];
        if (has_next) {
            const float4* __restrict__ rp = in + (size_t)next * 256u + lane;
            #pragma unroll
            for (int k = 0; k < 8; k++) nxt[k] = __ldcs(rp + 32 * k);
        }

        // Reduce current row
        float s = 0.0f;
        #pragma unroll
        for (int k = 0; k < 8; k++)
            s += (cur[k].x + cur[k].y) + (cur[k].z + cur[k].w);
        #pragma unroll
        for (int off = 16; off > 0; off >>= 1)
            s += __shfl_xor_sync(0xffffffffu, s, off);

        float inv = 1.0f / s;
        if (!isfinite(inv)) inv = 0.0f;          // reference: remove_nan_inf

        // Scale + store current row
        float4* __restrict__ wp = out + (size_t)row * 256u + lane;
        #pragma unroll
        for (int k = 0; k < 8; k++) {
            float4 v = cur[k];
            v.x *= inv; v.y *= inv; v.z *= inv; v.w *= inv;
            __stcs(wp + 32 * k, v);
        }

        if (!has_next) break;
        #pragma unroll
        for (int k = 0; k < 8; k++) cur[k] = nxt[k];
        row = next;
    }
}

extern "C" void kernel_launch(void* const* d_in, const int* in_sizes, int n_in,
                              void* d_out, int out_size) {
    (void)in_sizes; (void)n_in; (void)out_size;
    const float4* in  = (const float4*)d_in[0];
    float4*       out = (float4*)d_out;

    const unsigned n_rows = 2u * 32u * 1024u;    // 65536
    // One resident wave: 152 SMs (GB300) x 3 blocks (85-reg cap from
    // __launch_bounds__(256,3)). ~18 rows per warp, pipelined.
    const unsigned grid = 152u * 3u;
    normalizer_kernel<<<grid, 256>>>(in, out, n_rows);
}

// round 9
// speedup vs baseline: 1.1478x; 1.1462x over previous
#include <cuda_runtime.h>

// Row-wise normalization: out[r, :] = in[r, :] / sum(in[r, :])
// Rows = 2*32*1024 = 65536, row length = 1024 floats = 256 float4.
//
// Flat grid (best wall-clock family). TWO warps per row, 4 float4 per lane:
//  - data regs 16 instead of 32  -> ~30 regs total -> 8 blocks/SM (100% occ)
//  - MLP = 4 front-batched LDG.128 per thread (enough in-flight bytes)
//  - cross-warp reduce via NAMED pairwise barrier (bar.sync id, 64): each
//    row's warp pair syncs only with itself, no block-wide __syncthreads
//    coupling the 4 independent rows in a block.
__global__ void __launch_bounds__(256, 8)
normalizer_kernel(const float4* __restrict__ in, float4* __restrict__ out) {
    const unsigned tid  = threadIdx.x;
    const unsigned w    = tid >> 5;          // warp 0..7
    const unsigned lane = tid & 31u;
    const unsigned pair = w >> 1;            // row-pair 0..3
    const unsigned half = w & 1u;            // which half of the row
    const unsigned row  = blockIdx.x * 4u + pair;

    // This warp covers float4 indices [half*128, half*128+128)
    const size_t base = (size_t)row * 256u + half * 128u + lane;
    const float4* __restrict__ rp = in  + base;
    float4*       __restrict__ wp = out + base;

    float4 v[4];
    #pragma unroll
    for (int k = 0; k < 4; k++)
        v[k] = __ldcs(rp + 32 * k);          // 4 independent LDG.128

    float s = 0.0f;
    #pragma unroll
    for (int k = 0; k < 4; k++)
        s += (v[k].x + v[k].y) + (v[k].z + v[k].w);

    #pragma unroll
    for (int off = 16; off > 0; off >>= 1)
        s += __shfl_xor_sync(0xffffffffu, s, off);

    // Pairwise cross-warp reduce: 2-float smem exchange + 64-thread barrier
    __shared__ float part[8];
    if (lane == 0) part[w] = s;
    asm volatile("bar.sync %0, 64;" :: "r"(pair + 1) : "memory");
    const float deg = part[pair * 2] + part[pair * 2 + 1];

    float inv = 1.0f / deg;
    if (!isfinite(inv)) inv = 0.0f;          // reference: remove_nan_inf

    #pragma unroll
    for (int k = 0; k < 4; k++) {
        float4 t = v[k];
        t.x *= inv; t.y *= inv; t.z *= inv; t.w *= inv;
        __stcs(wp + 32 * k, t);
    }
}

extern "C" void kernel_launch(void* const* d_in, const int* in_sizes, int n_in,
                              void* d_out, int out_size) {
    (void)in_sizes; (void)n_in; (void)out_size;
    const float4* in  = (const float4*)d_in[0];
    float4*       out = (float4*)d_out;

    // 65536 rows, 4 rows per block -> 16384 blocks
    normalizer_kernel<<<65536 / 4, 256>>>(in, out);
}